// round 11
// baseline (speedup 1.0000x reference)
#include <cuda_runtime.h>
#include <cuda_fp16.h>
#include <math.h>
#include <stdint.h>

// Problem constants
#define T_TOK   2048
#define HDIM    1024
#define NEXP    16
#define IDIM    512
#define ISDIM   1024
#define TOPK    4
#define NGRP    4
#define EPG     4
#define SCALE_F 2.5f

#define BM 128
#define BN 128
#define BK 32
#define MAXSLOTS (8192 + NEXP*BM)    // 10240
#define SMS 40                        // smem stride in halves (32 + 8 pad)
#define TILEH (128 * SMS)
#define STAGE_BYTES (TILEH * 2)
#define NSTAGE 4
#define SMEM_TOTAL (2 * NSTAGE * STAGE_BYTES)   // 81920 B

// ---------------- scratch ----------------
__device__ float  g_topw[T_TOK*TOPK];
__device__ int    g_tope[T_TOK*TOPK];
__device__ int    g_slotmap[T_TOK*TOPK];
__device__ int    g_list[MAXSLOTS];
__device__ int    g_cnt[NEXP];
__device__ int    g_cur[NEXP];
__device__ int    g_off[NEXP+1];

__device__ __half h_x  [(size_t)T_TOK * HDIM];
__device__ __half h_W1 [(size_t)NEXP * IDIM * HDIM];
__device__ __half h_W2 [(size_t)NEXP * HDIM * IDIM];
__device__ __half h_Ws1[(size_t)ISDIM * HDIM];
__device__ __half h_Ws2[(size_t)HDIM * ISDIM];

__device__ __half g_hid[(size_t)MAXSLOTS * IDIM];
__device__ float  g_y  [(size_t)MAXSLOTS * HDIM];
__device__ __half g_hs [(size_t)T_TOK * ISDIM];
__device__ float  g_ys [(size_t)T_TOK * HDIM];

// ---------------- helpers ----------------
__device__ __forceinline__ uint32_t smem_u32(const void* p) {
    uint32_t a;
    asm("{ .reg .u64 t; cvta.to.shared.u64 t, %1; cvt.u32.u64 %0, t; }" : "=r"(a) : "l"(p));
    return a;
}
__device__ __forceinline__ void cp16(uint32_t dst, const void* src) {
    asm volatile("cp.async.cg.shared.global [%0], [%1], 16;" :: "r"(dst), "l"(src));
}
__device__ __forceinline__ void ldsm_x4(uint32_t* r, uint32_t addr) {
    asm volatile("ldmatrix.sync.aligned.m8n8.x4.shared.b16 {%0,%1,%2,%3}, [%4];"
                 : "=r"(r[0]), "=r"(r[1]), "=r"(r[2]), "=r"(r[3]) : "r"(addr));
}
__device__ __forceinline__ void mma_f16(float* c, const uint32_t* a, const uint32_t* b) {
    asm volatile(
        "mma.sync.aligned.m16n8k16.row.col.f32.f16.f16.f32 "
        "{%0,%1,%2,%3}, {%4,%5,%6,%7}, {%8,%9}, {%0,%1,%2,%3};"
        : "+f"(c[0]), "+f"(c[1]), "+f"(c[2]), "+f"(c[3])
        : "r"(a[0]), "r"(a[1]), "r"(a[2]), "r"(a[3]), "r"(b[0]), "r"(b[1]));
}

// ---------------- fp32 -> fp16 ----------------
__global__ void cvt_kernel(const float* __restrict__ src, __half* __restrict__ dst, int n4) {
    int i = blockIdx.x * 256 + threadIdx.x;
    int stride = gridDim.x * 256;
    for (; i < n4; i += stride) {
        float4 v = *(const float4*)(src + (size_t)i * 4);
        __half2 lo = __floats2half2_rn(v.x, v.y);
        __half2 hi = __floats2half2_rn(v.z, v.w);
        uint2 u;
        u.x = *(uint32_t*)&lo;
        u.y = *(uint32_t*)&hi;
        *(uint2*)(dst + (size_t)i * 4) = u;
    }
}

// ---------------- init ----------------
__global__ void init_kernel() {
    int i = blockIdx.x * 256 + threadIdx.x;
    if (i < NEXP) { g_cnt[i] = 0; g_cur[i] = 0; }
    if (i < MAXSLOTS) g_list[i] = -1;
}

// ---------------- router ----------------
__global__ void router_kernel(const float* __restrict__ x,
                              const float* __restrict__ Wg,
                              const float* __restrict__ bias) {
    int t = blockIdx.x;
    __shared__ float sx[HDIM];
    __shared__ float slog[NEXP];
    const float* xr = x + (size_t)t * HDIM;
    for (int i = threadIdx.x; i < HDIM; i += 128) sx[i] = xr[i];
    __syncthreads();
    int warp = threadIdx.x >> 5, lane = threadIdx.x & 31;
    for (int eo = 0; eo < 4; eo++) {
        int e = warp * 4 + eo;
        const float* w = Wg + (size_t)e * HDIM;
        float p = 0.f;
        for (int i = lane; i < HDIM; i += 32) p += sx[i] * w[i];
        #pragma unroll
        for (int o = 16; o; o >>= 1) p += __shfl_xor_sync(0xffffffffu, p, o);
        if (lane == 0) slog[e] = p;
    }
    __syncthreads();
    if (threadIdx.x == 0) {
        float sc[NEXP], ch[NEXP];
        #pragma unroll
        for (int e = 0; e < NEXP; e++) {
            sc[e] = 1.f / (1.f + expf(-slog[e]));
            ch[e] = sc[e] + bias[e];
        }
        float gs[NGRP];
        #pragma unroll
        for (int g = 0; g < NGRP; g++) {
            float m1 = -1e30f, m2 = -1e30f;
            #pragma unroll
            for (int k = 0; k < EPG; k++) {
                float v = ch[g*EPG + k];
                if (v > m1) { m2 = m1; m1 = v; } else if (v > m2) { m2 = v; }
            }
            gs[g] = m1 + m2;
        }
        int g1 = 0;
        for (int g = 1; g < NGRP; g++) if (gs[g] > gs[g1]) g1 = g;
        int g2 = -1;
        for (int g = 0; g < NGRP; g++) { if (g == g1) continue; if (g2 < 0 || gs[g] > gs[g2]) g2 = g; }
        float masked[NEXP];
        #pragma unroll
        for (int e = 0; e < NEXP; e++) {
            int g = e >> 2;
            masked[e] = (g == g1 || g == g2) ? ch[e] : 0.f;
        }
        int idx[TOPK]; float tw[TOPK]; float wsum = 0.f;
        #pragma unroll
        for (int j = 0; j < TOPK; j++) {
            int b = 0;
            for (int e = 1; e < NEXP; e++) if (masked[e] > masked[b]) b = e;
            idx[j] = b; tw[j] = sc[b]; wsum += sc[b];
            masked[b] = -1e30f;
        }
        float inv = SCALE_F / (wsum + 1e-20f);
        #pragma unroll
        for (int j = 0; j < TOPK; j++) {
            g_topw[t*TOPK + j] = tw[j] * inv;
            g_tope[t*TOPK + j] = idx[j];
            atomicAdd(&g_cnt[idx[j]], 1);
        }
    }
}

__global__ void scan_kernel() {
    if (threadIdx.x == 0) {
        int o = 0;
        for (int e = 0; e < NEXP; e++) {
            g_off[e] = o;
            o += ((g_cnt[e] + BM - 1) / BM) * BM;
        }
        g_off[NEXP] = o;
    }
}

__global__ void fill_kernel() {
    int t = blockIdx.x * 256 + threadIdx.x;
    if (t >= T_TOK) return;
    for (int j = 0; j < TOPK; j++) {
        int e = g_tope[t*TOPK + j];
        int pos = atomicAdd(&g_cur[e], 1);
        int slot = g_off[e] + pos;
        g_list[slot] = t;
        g_slotmap[t*TOPK + j] = slot;
    }
}

// ---------------- fp16 tensor-core GEMM (ldmatrix + 4-stage cp.async, 1 bar/iter) ----------------
template<bool GATHER, bool EXPERT, bool RELU2, typename CT>
__global__ void __launch_bounds__(256)
gemm_h(const __half* __restrict__ A, const __half* __restrict__ W,
       CT* __restrict__ C, int K, int Ntot, size_t wstride) {
    extern __shared__ __align__(16) __half dsm[];
    int row0 = blockIdx.x * BM;
    int e = 0;
    if (EXPERT) {
        int tot = g_off[NEXP];
        if (row0 >= tot) return;
        while (row0 >= g_off[e+1]) e++;
    }
    const __half* Wb = EXPERT ? (W + (size_t)e * wstride) : W;
    int n0 = blockIdx.y * BN;

    int tid  = threadIdx.x;
    int lane = tid & 31;
    int warp = tid >> 5;
    int wm = (warp & 1) * 64;
    int wn = (warp >> 1) * 32;

    uint32_t s0 = smem_u32(dsm);
    uint32_t aB[NSTAGE], bB[NSTAGE];
    #pragma unroll
    for (int s = 0; s < NSTAGE; s++) {
        aB[s] = s0 + s * STAGE_BYTES;
        bB[s] = s0 + (NSTAGE + s) * STAGE_BYTES;
    }

    int lrow = tid >> 1;
    int lcol = (tid & 1) * 16;
    uint32_t dOff = (uint32_t)(lrow * SMS + lcol) * 2;

    const __half* arow;
    if (GATHER) {
        int tok = g_list[row0 + lrow];
        arow = A + (size_t)(tok >= 0 ? tok : 0) * K;
    } else {
        arow = A + (size_t)(row0 + lrow) * K;
    }
    const __half* brow = Wb + (size_t)(n0 + lrow) * K;

    uint32_t aOff = (uint32_t)((wm + (lane & 15)) * SMS + (lane >> 4) * 8) * 2;
    uint32_t bOff = (uint32_t)((wn + ((lane >> 4) * 8) + (lane & 7)) * SMS + ((lane >> 3) & 1) * 8) * 2;

    float acc[4][4][4];
    #pragma unroll
    for (int i = 0; i < 4; i++)
        #pragma unroll
        for (int j = 0; j < 4; j++)
            #pragma unroll
            for (int q = 0; q < 4; q++) acc[i][j][q] = 0.f;

    int nt = K / BK;

    // prologue: issue tiles 0,1,2
    #pragma unroll
    for (int p = 0; p < 3; p++) {
        if (p < nt) {
            const __half* as = arow + p * BK + lcol;
            const __half* bs = brow + p * BK + lcol;
            cp16(aB[p] + dOff,      as);
            cp16(aB[p] + dOff + 16, as + 8);
            cp16(bB[p] + dOff,      bs);
            cp16(bB[p] + dOff + 16, bs + 8);
            asm volatile("cp.async.commit_group;");
        }
    }

    for (int kt = 0; kt < nt; kt++) {
        // ensure tile kt arrived: pending groups = min(nt - kt, 3)
        if (kt + 3 <= nt)       asm volatile("cp.async.wait_group 2;");
        else if (kt + 2 <= nt)  asm volatile("cp.async.wait_group 1;");
        else                    asm volatile("cp.async.wait_group 0;");
        __syncthreads();

        // issue tile kt+3 into stage (kt+3)%4 (last read at iter kt-1; all warps
        // passed this iteration's barrier after finishing it)
        if (kt + 3 < nt) {
            int s = (kt + 3) % NSTAGE;
            const __half* as = arow + (kt + 3) * BK + lcol;
            const __half* bs = brow + (kt + 3) * BK + lcol;
            cp16(aB[s] + dOff,      as);
            cp16(aB[s] + dOff + 16, as + 8);
            cp16(bB[s] + dOff,      bs);
            cp16(bB[s] + dOff + 16, bs + 8);
            asm volatile("cp.async.commit_group;");
        }

        int buf = kt % NSTAGE;
        uint32_t aT = aB[buf], bT = bB[buf];
        #pragma unroll
        for (int ks = 0; ks < 2; ks++) {
            uint32_t kkB = (uint32_t)(ks * 16) * 2;
            uint32_t af[4][4], bf[4][2];
            #pragma unroll
            for (int mf = 0; mf < 4; mf++)
                ldsm_x4(af[mf], aT + aOff + (uint32_t)(mf * 16 * SMS) * 2 + kkB);
            #pragma unroll
            for (int nfp = 0; nfp < 2; nfp++) {
                uint32_t r[4];
                ldsm_x4(r, bT + bOff + (uint32_t)(nfp * 16 * SMS) * 2 + kkB);
                bf[nfp*2+0][0] = r[0]; bf[nfp*2+0][1] = r[1];
                bf[nfp*2+1][0] = r[2]; bf[nfp*2+1][1] = r[3];
            }
            #pragma unroll
            for (int mf = 0; mf < 4; mf++)
                #pragma unroll
                for (int nf = 0; nf < 4; nf++)
                    mma_f16(acc[mf][nf], af[mf], bf[nf]);
        }
    }

    // epilogue
    int g  = lane >> 2;
    int c2 = (lane & 3) * 2;
    #pragma unroll
    for (int mf = 0; mf < 4; mf++) {
        int r = row0 + wm + mf * 16 + g;
        #pragma unroll
        for (int nf = 0; nf < 4; nf++) {
            int c = n0 + wn + nf * 8 + c2;
            float v0 = acc[mf][nf][0], v1 = acc[mf][nf][1];
            float v2 = acc[mf][nf][2], v3 = acc[mf][nf][3];
            if (RELU2) {
                v0 = fmaxf(v0, 0.f); v0 *= v0;
                v1 = fmaxf(v1, 0.f); v1 *= v1;
                v2 = fmaxf(v2, 0.f); v2 *= v2;
                v3 = fmaxf(v3, 0.f); v3 *= v3;
            }
            if (sizeof(CT) == 2) {
                __half2 lo = __floats2half2_rn(v0, v1);
                __half2 hi = __floats2half2_rn(v2, v3);
                *(uint32_t*)((__half*)C + (size_t) r      * Ntot + c) = *(uint32_t*)&lo;
                *(uint32_t*)((__half*)C + (size_t)(r + 8) * Ntot + c) = *(uint32_t*)&hi;
            } else {
                float2 lo; lo.x = v0; lo.y = v1;
                float2 hi; hi.x = v2; hi.y = v3;
                *(float2*)((float*)C + (size_t) r      * Ntot + c) = lo;
                *(float2*)((float*)C + (size_t)(r + 8) * Ntot + c) = hi;
            }
        }
    }
}

// ---------------- combine ----------------
__global__ void combine_kernel(float* __restrict__ out) {
    int t = blockIdx.x;
    int h = threadIdx.x * 4;
    float4 o = *(const float4*)&g_ys[(size_t)t * HDIM + h];
    #pragma unroll
    for (int j = 0; j < TOPK; j++) {
        int slot = g_slotmap[t*TOPK + j];
        float w = g_topw[t*TOPK + j];
        float4 v = *(const float4*)&g_y[(size_t)slot * HDIM + h];
        o.x += w * v.x; o.y += w * v.y; o.z += w * v.z; o.w += w * v.w;
    }
    *(float4*)&out[(size_t)t * HDIM + h] = o;
}

// ---------------- launch ----------------
extern "C" void kernel_launch(void* const* d_in, const int* in_sizes, int n_in,
                              void* d_out, int out_size) {
    const float *x = 0, *Wg = 0, *bias = 0, *W1 = 0, *W2 = 0, *Ws1 = 0, *Ws2 = 0;
    for (int i = 0; i < n_in; i++) {
        int sz = in_sizes[i];
        const float* p = (const float*)d_in[i];
        if      (sz == 2097152) { x = p; }
        else if (sz == 16384)   { Wg = p; }
        else if (sz == 16)      { bias = p; }
        else if (sz == 8388608) { if (!W1) W1 = p; else W2 = p; }
        else if (sz == 1048576) { if (!Ws1) Ws1 = p; else Ws2 = p; }
    }
    if (!x || !Wg || !bias || !W1 || !W2 || !Ws1 || !Ws2) {
        x = (const float*)d_in[0]; Wg = (const float*)d_in[1]; bias = (const float*)d_in[2];
        W1 = (const float*)d_in[3]; W2 = (const float*)d_in[4];
        Ws1 = (const float*)d_in[5]; Ws2 = (const float*)d_in[6];
    }
    float* out = (float*)d_out;

    __half *p_hx, *p_hW1, *p_hW2, *p_hWs1, *p_hWs2, *p_hid, *p_hs;
    float *p_y, *p_ys;
    cudaGetSymbolAddress((void**)&p_hx,   h_x);
    cudaGetSymbolAddress((void**)&p_hW1,  h_W1);
    cudaGetSymbolAddress((void**)&p_hW2,  h_W2);
    cudaGetSymbolAddress((void**)&p_hWs1, h_Ws1);
    cudaGetSymbolAddress((void**)&p_hWs2, h_Ws2);
    cudaGetSymbolAddress((void**)&p_hid,  g_hid);
    cudaGetSymbolAddress((void**)&p_hs,   g_hs);
    cudaGetSymbolAddress((void**)&p_y,    g_y);
    cudaGetSymbolAddress((void**)&p_ys,   g_ys);

    cudaFuncSetAttribute(gemm_h<true,  true,  true,  __half>, cudaFuncAttributeMaxDynamicSharedMemorySize, SMEM_TOTAL);
    cudaFuncSetAttribute(gemm_h<false, true,  false, float >, cudaFuncAttributeMaxDynamicSharedMemorySize, SMEM_TOTAL);
    cudaFuncSetAttribute(gemm_h<false, false, true,  __half>, cudaFuncAttributeMaxDynamicSharedMemorySize, SMEM_TOTAL);
    cudaFuncSetAttribute(gemm_h<false, false, false, float >, cudaFuncAttributeMaxDynamicSharedMemorySize, SMEM_TOTAL);

    // Launch order arranged so launch #6 (ncu -s 5 -c 1) is a GEMM.
    cvt_kernel<<<1024, 256>>>(x,   p_hx,   T_TOK*HDIM/4);        // 1
    cvt_kernel<<<512,  256>>>(Ws1, p_hWs1, ISDIM*HDIM/4);        // 2
    cvt_kernel<<<512,  256>>>(Ws2, p_hWs2, HDIM*ISDIM/4);        // 3
    cvt_kernel<<<2048, 256>>>(W1,  p_hW1,  NEXP*IDIM*HDIM/4);    // 4
    cvt_kernel<<<2048, 256>>>(W2,  p_hW2,  NEXP*HDIM*IDIM/4);    // 5

    // shared up: hs[t] = relu2( x[t] @ Ws1^T )                  // 6  <-- profiled
    gemm_h<false, false, true,  __half><<<dim3(T_TOK/BM,   ISDIM/BN), 256, SMEM_TOTAL>>>(p_hx,  p_hWs1, p_hs,  HDIM,  ISDIM, 0);

    init_kernel<<<(MAXSLOTS + 255) / 256, 256>>>();              // 7
    router_kernel<<<T_TOK, 128>>>(x, Wg, bias);                  // 8
    scan_kernel<<<1, 32>>>();                                    // 9
    fill_kernel<<<(T_TOK + 255) / 256, 256>>>();                 // 10

    // shared down: ys[t] = hs[t] @ Ws2^T                        // 11
    gemm_h<false, false, false, float ><<<dim3(T_TOK/BM,   HDIM/BN),  256, SMEM_TOTAL>>>(p_hs,  p_hWs2, p_ys,  ISDIM, HDIM,  0);
    // expert up: hid[slot] = relu2( x[g_list[slot]] @ W1[e]^T ) // 12
    gemm_h<true,  true,  true,  __half><<<dim3(MAXSLOTS/BM, IDIM/BN),  256, SMEM_TOTAL>>>(p_hx,  p_hW1,  p_hid, HDIM,  IDIM,  (size_t)IDIM*HDIM);
    // expert down: y[slot] = hid[slot] @ W2[e]^T                // 13
    gemm_h<false, true,  false, float ><<<dim3(MAXSLOTS/BM, HDIM/BN),  256, SMEM_TOTAL>>>(p_hid, p_hW2,  p_y,   IDIM,  HDIM,  (size_t)HDIM*IDIM);

    combine_kernel<<<T_TOK, 256>>>(out);                         // 14
}

// round 12
// speedup vs baseline: 1.1252x; 1.1252x over previous
#include <cuda_runtime.h>
#include <cuda_fp16.h>
#include <math.h>
#include <stdint.h>

// Problem constants
#define T_TOK   2048
#define HDIM    1024
#define NEXP    16
#define IDIM    512
#define ISDIM   1024
#define TOPK    4
#define NGRP    4
#define EPG     4
#define SCALE_F 2.5f

#define BM 128
#define BN 128
#define BK 32
#define MAXSLOTS (8192 + NEXP*BM)    // 10240
#define SMS 40                        // smem stride in halves (32 + 8 pad)
#define TILEH (128 * SMS)
#define STAGE_BYTES (TILEH * 2)
#define NSTAGE 4
#define SMEM_TOTAL (2 * NSTAGE * STAGE_BYTES)   // 81920 B

// ---------------- scratch ----------------
__device__ float  g_topw[T_TOK*TOPK];
__device__ int    g_tope[T_TOK*TOPK];
__device__ int    g_slotmap[T_TOK*TOPK];
__device__ int    g_list[MAXSLOTS];
__device__ int    g_cnt[NEXP];
__device__ int    g_cur[NEXP];
__device__ int    g_off[NEXP+1];

__device__ __half h_x  [(size_t)T_TOK * HDIM];
__device__ __half h_W1 [(size_t)NEXP * IDIM * HDIM];
__device__ __half h_W2 [(size_t)NEXP * HDIM * IDIM];
__device__ __half h_Ws1[(size_t)ISDIM * HDIM];
__device__ __half h_Ws2[(size_t)HDIM * ISDIM];

__device__ __half g_hid[(size_t)MAXSLOTS * IDIM];
__device__ float  g_y  [(size_t)MAXSLOTS * HDIM];
__device__ __half g_hs [(size_t)T_TOK * ISDIM];
__device__ float  g_ys [(size_t)T_TOK * HDIM];

// ---------------- helpers ----------------
__device__ __forceinline__ uint32_t smem_u32(const void* p) {
    uint32_t a;
    asm("{ .reg .u64 t; cvta.to.shared.u64 t, %1; cvt.u32.u64 %0, t; }" : "=r"(a) : "l"(p));
    return a;
}
__device__ __forceinline__ void cp16(uint32_t dst, const void* src) {
    asm volatile("cp.async.cg.shared.global [%0], [%1], 16;" :: "r"(dst), "l"(src));
}
__device__ __forceinline__ void ldsm_x4(uint32_t* r, uint32_t addr) {
    asm volatile("ldmatrix.sync.aligned.m8n8.x4.shared.b16 {%0,%1,%2,%3}, [%4];"
                 : "=r"(r[0]), "=r"(r[1]), "=r"(r[2]), "=r"(r[3]) : "r"(addr));
}
__device__ __forceinline__ void mma_f16(float* c, const uint32_t* a, const uint32_t* b) {
    asm volatile(
        "mma.sync.aligned.m16n8k16.row.col.f32.f16.f16.f32 "
        "{%0,%1,%2,%3}, {%4,%5,%6,%7}, {%8,%9}, {%0,%1,%2,%3};"
        : "+f"(c[0]), "+f"(c[1]), "+f"(c[2]), "+f"(c[3])
        : "r"(a[0]), "r"(a[1]), "r"(a[2]), "r"(a[3]), "r"(b[0]), "r"(b[1]));
}

// ---------------- single fused fp32->fp16 conversion ----------------
// segment boundaries in float4 units
#define C_X   524288u            // x:   2M elems
#define C_W1  2097152u           // W1:  8M
#define C_W2  2097152u
#define C_WS  262144u            // Ws1/Ws2: 1M each
#define C_TOT (C_X + C_W1 + C_W2 + 2*C_WS)   // 5242880
__global__ void cvt_all(const float* __restrict__ x,  const float* __restrict__ W1,
                        const float* __restrict__ W2, const float* __restrict__ Ws1,
                        const float* __restrict__ Ws2) {
    uint32_t i = blockIdx.x * 256 + threadIdx.x;
    if (i >= C_TOT) return;
    const float* s; __half* d; uint32_t off;
    if      (i < C_X)                     { s = x;   d = h_x;   off = i; }
    else if (i < C_X + C_W1)              { s = W1;  d = h_W1;  off = i - C_X; }
    else if (i < C_X + C_W1 + C_W2)       { s = W2;  d = h_W2;  off = i - C_X - C_W1; }
    else if (i < C_X + C_W1 + C_W2 + C_WS){ s = Ws1; d = h_Ws1; off = i - C_X - C_W1 - C_W2; }
    else                                  { s = Ws2; d = h_Ws2; off = i - C_X - C_W1 - C_W2 - C_WS; }
    float4 v = *(const float4*)(s + (size_t)off * 4);
    __half2 lo = __floats2half2_rn(v.x, v.y);
    __half2 hi = __floats2half2_rn(v.z, v.w);
    uint2 u;
    u.x = *(uint32_t*)&lo;
    u.y = *(uint32_t*)&hi;
    *(uint2*)(d + (size_t)off * 4) = u;
}

// ---------------- init ----------------
__global__ void init_kernel() {
    int i = blockIdx.x * 256 + threadIdx.x;
    if (i < NEXP) { g_cnt[i] = 0; g_cur[i] = 0; }
    if (i < MAXSLOTS) g_list[i] = -1;
}

// ---------------- router ----------------
__global__ void router_kernel(const float* __restrict__ x,
                              const float* __restrict__ Wg,
                              const float* __restrict__ bias) {
    int t = blockIdx.x;
    __shared__ float sx[HDIM];
    __shared__ float slog[NEXP];
    const float* xr = x + (size_t)t * HDIM;
    for (int i = threadIdx.x; i < HDIM; i += 128) sx[i] = xr[i];
    __syncthreads();
    int warp = threadIdx.x >> 5, lane = threadIdx.x & 31;
    for (int eo = 0; eo < 4; eo++) {
        int e = warp * 4 + eo;
        const float* w = Wg + (size_t)e * HDIM;
        float p = 0.f;
        for (int i = lane; i < HDIM; i += 32) p += sx[i] * w[i];
        #pragma unroll
        for (int o = 16; o; o >>= 1) p += __shfl_xor_sync(0xffffffffu, p, o);
        if (lane == 0) slog[e] = p;
    }
    __syncthreads();
    if (threadIdx.x == 0) {
        float sc[NEXP], ch[NEXP];
        #pragma unroll
        for (int e = 0; e < NEXP; e++) {
            sc[e] = 1.f / (1.f + expf(-slog[e]));
            ch[e] = sc[e] + bias[e];
        }
        float gs[NGRP];
        #pragma unroll
        for (int g = 0; g < NGRP; g++) {
            float m1 = -1e30f, m2 = -1e30f;
            #pragma unroll
            for (int k = 0; k < EPG; k++) {
                float v = ch[g*EPG + k];
                if (v > m1) { m2 = m1; m1 = v; } else if (v > m2) { m2 = v; }
            }
            gs[g] = m1 + m2;
        }
        int g1 = 0;
        for (int g = 1; g < NGRP; g++) if (gs[g] > gs[g1]) g1 = g;
        int g2 = -1;
        for (int g = 0; g < NGRP; g++) { if (g == g1) continue; if (g2 < 0 || gs[g] > gs[g2]) g2 = g; }
        float masked[NEXP];
        #pragma unroll
        for (int e = 0; e < NEXP; e++) {
            int g = e >> 2;
            masked[e] = (g == g1 || g == g2) ? ch[e] : 0.f;
        }
        int idx[TOPK]; float tw[TOPK]; float wsum = 0.f;
        #pragma unroll
        for (int j = 0; j < TOPK; j++) {
            int b = 0;
            for (int e = 1; e < NEXP; e++) if (masked[e] > masked[b]) b = e;
            idx[j] = b; tw[j] = sc[b]; wsum += sc[b];
            masked[b] = -1e30f;
        }
        float inv = SCALE_F / (wsum + 1e-20f);
        #pragma unroll
        for (int j = 0; j < TOPK; j++) {
            g_topw[t*TOPK + j] = tw[j] * inv;
            g_tope[t*TOPK + j] = idx[j];
            atomicAdd(&g_cnt[idx[j]], 1);
        }
    }
}

__global__ void scan_kernel() {
    if (threadIdx.x == 0) {
        int o = 0;
        for (int e = 0; e < NEXP; e++) {
            g_off[e] = o;
            o += ((g_cnt[e] + BM - 1) / BM) * BM;
        }
        g_off[NEXP] = o;
    }
}

__global__ void fill_kernel() {
    int t = blockIdx.x * 256 + threadIdx.x;
    if (t >= T_TOK) return;
    for (int j = 0; j < TOPK; j++) {
        int e = g_tope[t*TOPK + j];
        int pos = atomicAdd(&g_cur[e], 1);
        int slot = g_off[e] + pos;
        g_list[slot] = t;
        g_slotmap[t*TOPK + j] = slot;
    }
}

// ---------------- fused fp16 tensor-core GEMM (two sub-problems in one grid) ----------------
// Part p (p=0 for bx < blocks0, else p=1) computes:
//   Cp[row][n] = act( Ap_row . Wp[n] )  with Ap [.,Kp] fp16 row-major, Wp [Np? ,Kp] row-major.
// Flags per part: gather (A row via g_list), expert (W base from g_off expert id).
template<bool RELU2, typename CT>
__global__ void __launch_bounds__(256)
gemm_fused(const __half* A0, const __half* W0, CT* C0, int K0, int N0, int nblk0,
           int g0, int e0flag, size_t ws0, int blocks0,
           const __half* A1, const __half* W1p, CT* C1, int K1, int N1, int nblk1,
           int g1, int e1flag, size_t ws1) {
    extern __shared__ __align__(16) __half dsm[];

    int bx = blockIdx.x;
    const __half* A; const __half* W; CT* C;
    int K, Ntot, nblk, gather, expertF; size_t wstride;
    if (bx < blocks0) {
        A = A0; W = W0; C = C0; K = K0; Ntot = N0; nblk = nblk0;
        gather = g0; expertF = e0flag; wstride = ws0;
    } else {
        bx -= blocks0;
        A = A1; W = W1p; C = C1; K = K1; Ntot = N1; nblk = nblk1;
        gather = g1; expertF = e1flag; wstride = ws1;
    }
    int row0 = (bx / nblk) * BM;
    int n0   = (bx % nblk) * BN;

    if (expertF) {
        int tot = g_off[NEXP];
        if (row0 >= tot) return;
        int e = 0;
        while (row0 >= g_off[e+1]) e++;
        W += (size_t)e * wstride;
    }

    int tid  = threadIdx.x;
    int lane = tid & 31;
    int warp = tid >> 5;
    int wm = (warp & 1) * 64;
    int wn = (warp >> 1) * 32;

    uint32_t s0 = smem_u32(dsm);
    uint32_t aB[NSTAGE], bB[NSTAGE];
    #pragma unroll
    for (int s = 0; s < NSTAGE; s++) {
        aB[s] = s0 + s * STAGE_BYTES;
        bB[s] = s0 + (NSTAGE + s) * STAGE_BYTES;
    }

    int lrow = tid >> 1;
    int lcol = (tid & 1) * 16;
    uint32_t dOff = (uint32_t)(lrow * SMS + lcol) * 2;

    const __half* arow;
    if (gather) {
        int tok = g_list[row0 + lrow];
        arow = A + (size_t)(tok >= 0 ? tok : 0) * K;
    } else {
        arow = A + (size_t)(row0 + lrow) * K;
    }
    const __half* brow = W + (size_t)(n0 + lrow) * K;

    uint32_t aOff = (uint32_t)((wm + (lane & 15)) * SMS + (lane >> 4) * 8) * 2;
    uint32_t bOff = (uint32_t)((wn + ((lane >> 4) * 8) + (lane & 7)) * SMS + ((lane >> 3) & 1) * 8) * 2;

    float acc[4][4][4];
    #pragma unroll
    for (int i = 0; i < 4; i++)
        #pragma unroll
        for (int j = 0; j < 4; j++)
            #pragma unroll
            for (int q = 0; q < 4; q++) acc[i][j][q] = 0.f;

    int nt = K / BK;

    #pragma unroll
    for (int p = 0; p < 3; p++) {
        if (p < nt) {
            const __half* as = arow + p * BK + lcol;
            const __half* bs = brow + p * BK + lcol;
            cp16(aB[p] + dOff,      as);
            cp16(aB[p] + dOff + 16, as + 8);
            cp16(bB[p] + dOff,      bs);
            cp16(bB[p] + dOff + 16, bs + 8);
            asm volatile("cp.async.commit_group;");
        }
    }

    for (int kt = 0; kt < nt; kt++) {
        if (kt + 3 <= nt)       asm volatile("cp.async.wait_group 2;");
        else if (kt + 2 <= nt)  asm volatile("cp.async.wait_group 1;");
        else                    asm volatile("cp.async.wait_group 0;");
        __syncthreads();

        if (kt + 3 < nt) {
            int s = (kt + 3) % NSTAGE;
            const __half* as = arow + (kt + 3) * BK + lcol;
            const __half* bs = brow + (kt + 3) * BK + lcol;
            cp16(aB[s] + dOff,      as);
            cp16(aB[s] + dOff + 16, as + 8);
            cp16(bB[s] + dOff,      bs);
            cp16(bB[s] + dOff + 16, bs + 8);
            asm volatile("cp.async.commit_group;");
        }

        int buf = kt % NSTAGE;
        uint32_t aT = aB[buf], bT = bB[buf];
        #pragma unroll
        for (int ks = 0; ks < 2; ks++) {
            uint32_t kkB = (uint32_t)(ks * 16) * 2;
            uint32_t af[4][4], bf[4][2];
            #pragma unroll
            for (int mf = 0; mf < 4; mf++)
                ldsm_x4(af[mf], aT + aOff + (uint32_t)(mf * 16 * SMS) * 2 + kkB);
            #pragma unroll
            for (int nfp = 0; nfp < 2; nfp++) {
                uint32_t r[4];
                ldsm_x4(r, bT + bOff + (uint32_t)(nfp * 16 * SMS) * 2 + kkB);
                bf[nfp*2+0][0] = r[0]; bf[nfp*2+0][1] = r[1];
                bf[nfp*2+1][0] = r[2]; bf[nfp*2+1][1] = r[3];
            }
            #pragma unroll
            for (int mf = 0; mf < 4; mf++)
                #pragma unroll
                for (int nf = 0; nf < 4; nf++)
                    mma_f16(acc[mf][nf], af[mf], bf[nf]);
        }
    }

    int g  = lane >> 2;
    int c2 = (lane & 3) * 2;
    #pragma unroll
    for (int mf = 0; mf < 4; mf++) {
        int r = row0 + wm + mf * 16 + g;
        #pragma unroll
        for (int nf = 0; nf < 4; nf++) {
            int c = n0 + wn + nf * 8 + c2;
            float v0 = acc[mf][nf][0], v1 = acc[mf][nf][1];
            float v2 = acc[mf][nf][2], v3 = acc[mf][nf][3];
            if (RELU2) {
                v0 = fmaxf(v0, 0.f); v0 *= v0;
                v1 = fmaxf(v1, 0.f); v1 *= v1;
                v2 = fmaxf(v2, 0.f); v2 *= v2;
                v3 = fmaxf(v3, 0.f); v3 *= v3;
            }
            if (sizeof(CT) == 2) {
                __half2 lo = __floats2half2_rn(v0, v1);
                __half2 hi = __floats2half2_rn(v2, v3);
                *(uint32_t*)((__half*)C + (size_t) r      * Ntot + c) = *(uint32_t*)&lo;
                *(uint32_t*)((__half*)C + (size_t)(r + 8) * Ntot + c) = *(uint32_t*)&hi;
            } else {
                float2 lo; lo.x = v0; lo.y = v1;
                float2 hi; hi.x = v2; hi.y = v3;
                *(float2*)((float*)C + (size_t) r      * Ntot + c) = lo;
                *(float2*)((float*)C + (size_t)(r + 8) * Ntot + c) = hi;
            }
        }
    }
}

// ---------------- combine ----------------
__global__ void combine_kernel(float* __restrict__ out) {
    int t = blockIdx.x;
    int h = threadIdx.x * 4;
    float4 o = *(const float4*)&g_ys[(size_t)t * HDIM + h];
    #pragma unroll
    for (int j = 0; j < TOPK; j++) {
        int slot = g_slotmap[t*TOPK + j];
        float w = g_topw[t*TOPK + j];
        float4 v = *(const float4*)&g_y[(size_t)slot * HDIM + h];
        o.x += w * v.x; o.y += w * v.y; o.z += w * v.z; o.w += w * v.w;
    }
    *(float4*)&out[(size_t)t * HDIM + h] = o;
}

// ---------------- launch ----------------
extern "C" void kernel_launch(void* const* d_in, const int* in_sizes, int n_in,
                              void* d_out, int out_size) {
    const float *x = 0, *Wg = 0, *bias = 0, *W1 = 0, *W2 = 0, *Ws1 = 0, *Ws2 = 0;
    for (int i = 0; i < n_in; i++) {
        int sz = in_sizes[i];
        const float* p = (const float*)d_in[i];
        if      (sz == 2097152) { x = p; }
        else if (sz == 16384)   { Wg = p; }
        else if (sz == 16)      { bias = p; }
        else if (sz == 8388608) { if (!W1) W1 = p; else W2 = p; }
        else if (sz == 1048576) { if (!Ws1) Ws1 = p; else Ws2 = p; }
    }
    if (!x || !Wg || !bias || !W1 || !W2 || !Ws1 || !Ws2) {
        x = (const float*)d_in[0]; Wg = (const float*)d_in[1]; bias = (const float*)d_in[2];
        W1 = (const float*)d_in[3]; W2 = (const float*)d_in[4];
        Ws1 = (const float*)d_in[5]; Ws2 = (const float*)d_in[6];
    }
    float* out = (float*)d_out;

    __half *p_hx, *p_hW1, *p_hW2, *p_hWs1, *p_hWs2, *p_hid, *p_hs;
    float *p_y, *p_ys;
    cudaGetSymbolAddress((void**)&p_hx,   h_x);
    cudaGetSymbolAddress((void**)&p_hW1,  h_W1);
    cudaGetSymbolAddress((void**)&p_hW2,  h_W2);
    cudaGetSymbolAddress((void**)&p_hWs1, h_Ws1);
    cudaGetSymbolAddress((void**)&p_hWs2, h_Ws2);
    cudaGetSymbolAddress((void**)&p_hid,  g_hid);
    cudaGetSymbolAddress((void**)&p_hs,   g_hs);
    cudaGetSymbolAddress((void**)&p_y,    g_y);
    cudaGetSymbolAddress((void**)&p_ys,   g_ys);

    cudaFuncSetAttribute(gemm_fused<true,  __half>, cudaFuncAttributeMaxDynamicSharedMemorySize, SMEM_TOTAL);
    cudaFuncSetAttribute(gemm_fused<false, float >, cudaFuncAttributeMaxDynamicSharedMemorySize, SMEM_TOTAL);

    init_kernel<<<(MAXSLOTS + 255) / 256, 256>>>();                        // 1
    router_kernel<<<T_TOK, 128>>>(x, Wg, bias);                            // 2
    scan_kernel<<<1, 32>>>();                                              // 3
    fill_kernel<<<(T_TOK + 255) / 256, 256>>>();                           // 4
    cvt_all<<<(C_TOT + 255) / 256, 256>>>(x, W1, W2, Ws1, Ws2);            // 5

    // fused UP: part0 = expert up (gather+expert, 320 blocks), part1 = shared up (128 blocks)
    {
        int eBlocks = (MAXSLOTS / BM) * (IDIM / BN);    // 320
        int sBlocks = (T_TOK / BM) * (ISDIM / BN);      // 128
        gemm_fused<true, __half><<<eBlocks + sBlocks, 256, SMEM_TOTAL>>>(  // 6
            p_hx,  p_hW1,  p_hid, HDIM, IDIM,  IDIM / BN,  1, 1, (size_t)IDIM * HDIM, eBlocks,
            p_hx,  p_hWs1, p_hs,  HDIM, ISDIM, ISDIM / BN, 0, 0, 0);
    }
    // fused DOWN: part0 = shared down (K=1024, 128 blocks, runs in wave 1), part1 = expert down (K=512, 640)
    {
        int sBlocks = (T_TOK / BM) * (HDIM / BN);       // 128
        int eBlocks = (MAXSLOTS / BM) * (HDIM / BN);    // 640
        gemm_fused<false, float><<<sBlocks + eBlocks, 256, SMEM_TOTAL>>>(  // 7
            p_hs,  p_hWs2, p_ys,  ISDIM, HDIM, HDIM / BN, 0, 0, 0, sBlocks,
            p_hid, p_hW2,  p_y,   IDIM,  HDIM, HDIM / BN, 0, 1, (size_t)HDIM * IDIM);
    }

    combine_kernel<<<T_TOK, 256>>>(out);                                   // 8
}

// round 13
// speedup vs baseline: 1.1733x; 1.0427x over previous
#include <cuda_runtime.h>
#include <cuda_fp16.h>
#include <math.h>
#include <stdint.h>

// Problem constants
#define T_TOK   2048
#define HDIM    1024
#define NEXP    16
#define IDIM    512
#define ISDIM   1024
#define TOPK    4
#define NGRP    4
#define EPG     4
#define SCALE_F 2.5f

#define BM 128
#define BN 128
#define BK 32
#define MAXSLOTS (8192 + NEXP*BM)    // 10240
#define SMS 40                        // smem stride in halves (32 + 8 pad)
#define TILEH (128 * SMS)
#define STAGE_BYTES (TILEH * 2)
#define NSTAGE 4
#define SMEM_TOTAL (2 * NSTAGE * STAGE_BYTES)   // 81920 B

// tile counts
#define N_EU 320     // expert up:  80 rb x 4 bn
#define N_SU 128     // shared up:  16 rb x 8 bn
#define N_ED 640     // expert dn:  80 rb x 8 bn
#define N_SD 128     // shared dn:  16 rb x 8 bn
#define NTILES (N_EU + N_SU + N_ED + N_SD)   // 1216
#define N_DN  (N_ED + N_SD)                  // 768

// ---------------- scratch ----------------
__device__ float  g_topw[T_TOK*TOPK];
__device__ int    g_tope[T_TOK*TOPK];
__device__ int    g_slotmap[T_TOK*TOPK];
__device__ int    g_list[MAXSLOTS];
__device__ int    g_cnt[NEXP];
__device__ int    g_cur[NEXP];
__device__ int    g_off[NEXP+1];

__device__ int    g_tix;
__device__ int    g_done_eu[80];
__device__ int    g_done_su[16];
__device__ int    g_done_dn;

__device__ __half h_x  [(size_t)T_TOK * HDIM];
__device__ __half h_W1 [(size_t)NEXP * IDIM * HDIM];
__device__ __half h_W2 [(size_t)NEXP * HDIM * IDIM];
__device__ __half h_Ws1[(size_t)ISDIM * HDIM];
__device__ __half h_Ws2[(size_t)HDIM * ISDIM];

__device__ __half g_hid[(size_t)MAXSLOTS * IDIM];
__device__ float  g_y  [(size_t)MAXSLOTS * HDIM];
__device__ __half g_hs [(size_t)T_TOK * ISDIM];
__device__ float  g_ys [(size_t)T_TOK * HDIM];

// ---------------- helpers ----------------
__device__ __forceinline__ uint32_t smem_u32(const void* p) {
    uint32_t a;
    asm("{ .reg .u64 t; cvta.to.shared.u64 t, %1; cvt.u32.u64 %0, t; }" : "=r"(a) : "l"(p));
    return a;
}
__device__ __forceinline__ void cp16(uint32_t dst, const void* src) {
    asm volatile("cp.async.cg.shared.global [%0], [%1], 16;" :: "r"(dst), "l"(src));
}
__device__ __forceinline__ void ldsm_x4(uint32_t* r, uint32_t addr) {
    asm volatile("ldmatrix.sync.aligned.m8n8.x4.shared.b16 {%0,%1,%2,%3}, [%4];"
                 : "=r"(r[0]), "=r"(r[1]), "=r"(r[2]), "=r"(r[3]) : "r"(addr));
}
__device__ __forceinline__ void mma_f16(float* c, const uint32_t* a, const uint32_t* b) {
    asm volatile(
        "mma.sync.aligned.m16n8k16.row.col.f32.f16.f16.f32 "
        "{%0,%1,%2,%3}, {%4,%5,%6,%7}, {%8,%9}, {%0,%1,%2,%3};"
        : "+f"(c[0]), "+f"(c[1]), "+f"(c[2]), "+f"(c[3])
        : "r"(a[0]), "r"(a[1]), "r"(a[2]), "r"(a[3]), "r"(b[0]), "r"(b[1]));
}

// ---------------- single fused fp32->fp16 conversion ----------------
#define C_X   524288u
#define C_W1  2097152u
#define C_W2  2097152u
#define C_WS  262144u
#define C_TOT (C_X + C_W1 + C_W2 + 2*C_WS)
__global__ void cvt_all(const float* __restrict__ x,  const float* __restrict__ W1,
                        const float* __restrict__ W2, const float* __restrict__ Ws1,
                        const float* __restrict__ Ws2) {
    uint32_t i = blockIdx.x * 256 + threadIdx.x;
    if (i >= C_TOT) return;
    const float* s; __half* d; uint32_t off;
    if      (i < C_X)                     { s = x;   d = h_x;   off = i; }
    else if (i < C_X + C_W1)              { s = W1;  d = h_W1;  off = i - C_X; }
    else if (i < C_X + C_W1 + C_W2)       { s = W2;  d = h_W2;  off = i - C_X - C_W1; }
    else if (i < C_X + C_W1 + C_W2 + C_WS){ s = Ws1; d = h_Ws1; off = i - C_X - C_W1 - C_W2; }
    else                                  { s = Ws2; d = h_Ws2; off = i - C_X - C_W1 - C_W2 - C_WS; }
    float4 v = *(const float4*)(s + (size_t)off * 4);
    __half2 lo = __floats2half2_rn(v.x, v.y);
    __half2 hi = __floats2half2_rn(v.z, v.w);
    uint2 u;
    u.x = *(uint32_t*)&lo;
    u.y = *(uint32_t*)&hi;
    *(uint2*)(d + (size_t)off * 4) = u;
}

// ---------------- init ----------------
__global__ void init_kernel() {
    int i = blockIdx.x * 256 + threadIdx.x;
    if (i < NEXP) { g_cnt[i] = 0; g_cur[i] = 0; }
    if (i < MAXSLOTS) g_list[i] = -1;
    if (i == 0) { g_tix = 0; g_done_dn = 0; }
    if (i < 80) g_done_eu[i] = 0;
    if (i < 16) g_done_su[i] = 0;
}

// ---------------- router ----------------
__global__ void router_kernel(const float* __restrict__ x,
                              const float* __restrict__ Wg,
                              const float* __restrict__ bias) {
    int t = blockIdx.x;
    __shared__ float sx[HDIM];
    __shared__ float slog[NEXP];
    const float* xr = x + (size_t)t * HDIM;
    for (int i = threadIdx.x; i < HDIM; i += 128) sx[i] = xr[i];
    __syncthreads();
    int warp = threadIdx.x >> 5, lane = threadIdx.x & 31;
    for (int eo = 0; eo < 4; eo++) {
        int e = warp * 4 + eo;
        const float* w = Wg + (size_t)e * HDIM;
        float p = 0.f;
        for (int i = lane; i < HDIM; i += 32) p += sx[i] * w[i];
        #pragma unroll
        for (int o = 16; o; o >>= 1) p += __shfl_xor_sync(0xffffffffu, p, o);
        if (lane == 0) slog[e] = p;
    }
    __syncthreads();
    if (threadIdx.x == 0) {
        float sc[NEXP], ch[NEXP];
        #pragma unroll
        for (int e = 0; e < NEXP; e++) {
            sc[e] = 1.f / (1.f + expf(-slog[e]));
            ch[e] = sc[e] + bias[e];
        }
        float gs[NGRP];
        #pragma unroll
        for (int g = 0; g < NGRP; g++) {
            float m1 = -1e30f, m2 = -1e30f;
            #pragma unroll
            for (int k = 0; k < EPG; k++) {
                float v = ch[g*EPG + k];
                if (v > m1) { m2 = m1; m1 = v; } else if (v > m2) { m2 = v; }
            }
            gs[g] = m1 + m2;
        }
        int g1 = 0;
        for (int g = 1; g < NGRP; g++) if (gs[g] > gs[g1]) g1 = g;
        int g2 = -1;
        for (int g = 0; g < NGRP; g++) { if (g == g1) continue; if (g2 < 0 || gs[g] > gs[g2]) g2 = g; }
        float masked[NEXP];
        #pragma unroll
        for (int e = 0; e < NEXP; e++) {
            int g = e >> 2;
            masked[e] = (g == g1 || g == g2) ? ch[e] : 0.f;
        }
        int idx[TOPK]; float tw[TOPK]; float wsum = 0.f;
        #pragma unroll
        for (int j = 0; j < TOPK; j++) {
            int b = 0;
            for (int e = 1; e < NEXP; e++) if (masked[e] > masked[b]) b = e;
            idx[j] = b; tw[j] = sc[b]; wsum += sc[b];
            masked[b] = -1e30f;
        }
        float inv = SCALE_F / (wsum + 1e-20f);
        #pragma unroll
        for (int j = 0; j < TOPK; j++) {
            g_topw[t*TOPK + j] = tw[j] * inv;
            g_tope[t*TOPK + j] = idx[j];
            atomicAdd(&g_cnt[idx[j]], 1);
        }
    }
}

__global__ void scan_kernel() {
    if (threadIdx.x == 0) {
        int o = 0;
        for (int e = 0; e < NEXP; e++) {
            g_off[e] = o;
            o += ((g_cnt[e] + BM - 1) / BM) * BM;
        }
        g_off[NEXP] = o;
    }
}

__global__ void fill_kernel() {
    int t = blockIdx.x * 256 + threadIdx.x;
    if (t >= T_TOK) return;
    for (int j = 0; j < TOPK; j++) {
        int e = g_tope[t*TOPK + j];
        int pos = atomicAdd(&g_cur[e], 1);
        int slot = g_off[e] + pos;
        g_list[slot] = t;
        g_slotmap[t*TOPK + j] = slot;
    }
}

// ---------------- persistent MoE kernel: all 4 GEMMs + combine ----------------
__global__ void __launch_bounds__(256)
moe_persistent(float* __restrict__ out) {
    extern __shared__ __align__(16) __half dsm[];
    __shared__ int s_tix;

    int tid  = threadIdx.x;
    int lane = tid & 31;
    int warp = tid >> 5;
    int wm = (warp & 1) * 64;
    int wn = (warp >> 1) * 32;

    uint32_t s0 = smem_u32(dsm);
    uint32_t aB[NSTAGE], bB[NSTAGE];
    #pragma unroll
    for (int s = 0; s < NSTAGE; s++) {
        aB[s] = s0 + s * STAGE_BYTES;
        bB[s] = s0 + (NSTAGE + s) * STAGE_BYTES;
    }

    int lrow = tid >> 1;
    int lcol = (tid & 1) * 16;
    uint32_t dOff = (uint32_t)(lrow * SMS + lcol) * 2;
    uint32_t aOff = (uint32_t)((wm + (lane & 15)) * SMS + (lane >> 4) * 8) * 2;
    uint32_t bOff = (uint32_t)((wn + ((lane >> 4) * 8) + (lane & 7)) * SMS + ((lane >> 3) & 1) * 8) * 2;

    while (true) {
        if (tid == 0) s_tix = atomicAdd(&g_tix, 1);
        __syncthreads();
        int tix = s_tix;
        if (tix >= NTILES) break;

        // ---- decode tile ----
        const __half *A, *W;
        void* C;
        int K, Ntot, relu, outH, gather;
        int row0, n0;
        int* doneCnt;
        int* waitCnt = 0; int waitNeed = 0;
        bool skip = false;

        if (tix < N_EU) {                       // expert up
            int rb = tix >> 2, bn = tix & 3;
            row0 = rb * BM; n0 = bn * BN;
            A = h_x; gather = 1; K = HDIM; Ntot = IDIM;
            C = (void*)g_hid; relu = 1; outH = 1;
            doneCnt = &g_done_eu[rb];
            W = h_W1;
            int tot = g_off[NEXP];
            if (row0 >= tot) skip = true;
            else {
                int eid = 0;
                while (row0 >= g_off[eid+1]) eid++;
                W = h_W1 + (size_t)eid * IDIM * HDIM;
            }
        } else if (tix < N_EU + N_SU) {         // shared up
            int i2 = tix - N_EU; int rb = i2 >> 3, bn = i2 & 7;
            row0 = rb * BM; n0 = bn * BN;
            A = h_x; gather = 0; W = h_Ws1; K = HDIM; Ntot = ISDIM;
            C = (void*)g_hs; relu = 1; outH = 1;
            doneCnt = &g_done_su[rb];
        } else if (tix < N_EU + N_SU + N_ED) {  // expert down
            int i2 = tix - N_EU - N_SU; int rb = i2 >> 3, bn = i2 & 7;
            row0 = rb * BM; n0 = bn * BN;
            A = g_hid; gather = 0; K = IDIM; Ntot = HDIM;
            C = (void*)g_y; relu = 0; outH = 0;
            doneCnt = &g_done_dn;
            W = h_W2;
            int tot = g_off[NEXP];
            if (row0 >= tot) skip = true;
            else {
                int eid = 0;
                while (row0 >= g_off[eid+1]) eid++;
                W = h_W2 + (size_t)eid * HDIM * IDIM;
                waitCnt = &g_done_eu[rb]; waitNeed = 4;
            }
        } else {                                // shared down
            int i2 = tix - N_EU - N_SU - N_ED; int rb = i2 >> 3, bn = i2 & 7;
            row0 = rb * BM; n0 = bn * BN;
            A = g_hs; gather = 0; W = h_Ws2; K = ISDIM; Ntot = HDIM;
            C = (void*)g_ys; relu = 0; outH = 0;
            doneCnt = &g_done_dn;
            waitCnt = &g_done_su[rb]; waitNeed = 8;
        }

        if (skip) {
            if (tid == 0) atomicAdd(doneCnt, 1);
            continue;
        }
        if (waitCnt) {
            if (tid == 0) {
                while (atomicAdd(waitCnt, 0) < waitNeed) __nanosleep(64);
                __threadfence();
            }
            __syncthreads();
        }

        // ---- mainloop ----
        const __half* arow;
        if (gather) {
            int tok = g_list[row0 + lrow];
            arow = A + (size_t)(tok >= 0 ? tok : 0) * K;
        } else {
            arow = A + (size_t)(row0 + lrow) * K;
        }
        const __half* brow = W + (size_t)(n0 + lrow) * K;

        float acc[4][4][4];
        #pragma unroll
        for (int i = 0; i < 4; i++)
            #pragma unroll
            for (int j = 0; j < 4; j++)
                #pragma unroll
                for (int q = 0; q < 4; q++) acc[i][j][q] = 0.f;

        int nt = K / BK;

        #pragma unroll
        for (int p = 0; p < 3; p++) {
            if (p < nt) {
                const __half* as = arow + p * BK + lcol;
                const __half* bs = brow + p * BK + lcol;
                cp16(aB[p] + dOff,      as);
                cp16(aB[p] + dOff + 16, as + 8);
                cp16(bB[p] + dOff,      bs);
                cp16(bB[p] + dOff + 16, bs + 8);
                asm volatile("cp.async.commit_group;");
            }
        }

        for (int kt = 0; kt < nt; kt++) {
            if (kt + 3 <= nt)       asm volatile("cp.async.wait_group 2;");
            else if (kt + 2 <= nt)  asm volatile("cp.async.wait_group 1;");
            else                    asm volatile("cp.async.wait_group 0;");
            __syncthreads();

            if (kt + 3 < nt) {
                int s = (kt + 3) % NSTAGE;
                const __half* as = arow + (kt + 3) * BK + lcol;
                const __half* bs = brow + (kt + 3) * BK + lcol;
                cp16(aB[s] + dOff,      as);
                cp16(aB[s] + dOff + 16, as + 8);
                cp16(bB[s] + dOff,      bs);
                cp16(bB[s] + dOff + 16, bs + 8);
                asm volatile("cp.async.commit_group;");
            }

            int buf = kt % NSTAGE;
            uint32_t aT = aB[buf], bT = bB[buf];
            #pragma unroll
            for (int ks = 0; ks < 2; ks++) {
                uint32_t kkB = (uint32_t)(ks * 16) * 2;
                uint32_t af[4][4], bf[4][2];
                #pragma unroll
                for (int mf = 0; mf < 4; mf++)
                    ldsm_x4(af[mf], aT + aOff + (uint32_t)(mf * 16 * SMS) * 2 + kkB);
                #pragma unroll
                for (int nfp = 0; nfp < 2; nfp++) {
                    uint32_t r[4];
                    ldsm_x4(r, bT + bOff + (uint32_t)(nfp * 16 * SMS) * 2 + kkB);
                    bf[nfp*2+0][0] = r[0]; bf[nfp*2+0][1] = r[1];
                    bf[nfp*2+1][0] = r[2]; bf[nfp*2+1][1] = r[3];
                }
                #pragma unroll
                for (int mf = 0; mf < 4; mf++)
                    #pragma unroll
                    for (int nf = 0; nf < 4; nf++)
                        mma_f16(acc[mf][nf], af[mf], bf[nf]);
            }
        }

        // ---- epilogue ----
        int gq = lane >> 2;
        int c2 = (lane & 3) * 2;
        #pragma unroll
        for (int mf = 0; mf < 4; mf++) {
            int r = row0 + wm + mf * 16 + gq;
            #pragma unroll
            for (int nf = 0; nf < 4; nf++) {
                int c = n0 + wn + nf * 8 + c2;
                float v0 = acc[mf][nf][0], v1 = acc[mf][nf][1];
                float v2 = acc[mf][nf][2], v3 = acc[mf][nf][3];
                if (relu) {
                    v0 = fmaxf(v0, 0.f); v0 *= v0;
                    v1 = fmaxf(v1, 0.f); v1 *= v1;
                    v2 = fmaxf(v2, 0.f); v2 *= v2;
                    v3 = fmaxf(v3, 0.f); v3 *= v3;
                }
                if (outH) {
                    __half2 lo = __floats2half2_rn(v0, v1);
                    __half2 hi = __floats2half2_rn(v2, v3);
                    *(uint32_t*)((__half*)C + (size_t) r      * Ntot + c) = *(uint32_t*)&lo;
                    *(uint32_t*)((__half*)C + (size_t)(r + 8) * Ntot + c) = *(uint32_t*)&hi;
                } else {
                    float2 lo; lo.x = v0; lo.y = v1;
                    float2 hi; hi.x = v2; hi.y = v3;
                    *(float2*)((float*)C + (size_t) r      * Ntot + c) = lo;
                    *(float2*)((float*)C + (size_t)(r + 8) * Ntot + c) = hi;
                }
            }
        }

        __threadfence();
        __syncthreads();
        if (tid == 0) atomicAdd(doneCnt, 1);
    }

    // ---- combine phase ----
    if (tid == 0) {
        while (atomicAdd(&g_done_dn, 0) < N_DN) __nanosleep(64);
        __threadfence();
    }
    __syncthreads();

    for (int t = blockIdx.x; t < T_TOK; t += gridDim.x) {
        int h = tid * 4;
        float4 o = *(const float4*)&g_ys[(size_t)t * HDIM + h];
        #pragma unroll
        for (int j = 0; j < TOPK; j++) {
            int slot = g_slotmap[t*TOPK + j];
            float w = g_topw[t*TOPK + j];
            float4 v = *(const float4*)&g_y[(size_t)slot * HDIM + h];
            o.x += w * v.x; o.y += w * v.y; o.z += w * v.z; o.w += w * v.w;
        }
        *(float4*)&out[(size_t)t * HDIM + h] = o;
    }
}

// ---------------- launch ----------------
extern "C" void kernel_launch(void* const* d_in, const int* in_sizes, int n_in,
                              void* d_out, int out_size) {
    const float *x = 0, *Wg = 0, *bias = 0, *W1 = 0, *W2 = 0, *Ws1 = 0, *Ws2 = 0;
    for (int i = 0; i < n_in; i++) {
        int sz = in_sizes[i];
        const float* p = (const float*)d_in[i];
        if      (sz == 2097152) { x = p; }
        else if (sz == 16384)   { Wg = p; }
        else if (sz == 16)      { bias = p; }
        else if (sz == 8388608) { if (!W1) W1 = p; else W2 = p; }
        else if (sz == 1048576) { if (!Ws1) Ws1 = p; else Ws2 = p; }
    }
    if (!x || !Wg || !bias || !W1 || !W2 || !Ws1 || !Ws2) {
        x = (const float*)d_in[0]; Wg = (const float*)d_in[1]; bias = (const float*)d_in[2];
        W1 = (const float*)d_in[3]; W2 = (const float*)d_in[4];
        Ws1 = (const float*)d_in[5]; Ws2 = (const float*)d_in[6];
    }
    float* out = (float*)d_out;

    cudaFuncSetAttribute(moe_persistent, cudaFuncAttributeMaxDynamicSharedMemorySize, SMEM_TOTAL);

    // persistent grid: all CTAs must be resident (spin-wait safety)
    int smCount = 148, occ = 1;
    cudaDeviceGetAttribute(&smCount, cudaDevAttrMultiProcessorCount, 0);
    cudaOccupancyMaxActiveBlocksPerMultiprocessor(&occ, moe_persistent, 256, SMEM_TOTAL);
    if (occ < 1) occ = 1;
    int grid = smCount * occ;

    init_kernel<<<(MAXSLOTS + 255) / 256, 256>>>();                 // 1
    router_kernel<<<T_TOK, 128>>>(x, Wg, bias);                     // 2
    scan_kernel<<<1, 32>>>();                                       // 3
    fill_kernel<<<(T_TOK + 255) / 256, 256>>>();                    // 4
    cvt_all<<<(C_TOT + 255) / 256, 256>>>(x, W1, W2, Ws1, Ws2);     // 5
    moe_persistent<<<grid, 256, SMEM_TOTAL>>>(out);                 // 6
}